// round 12
// baseline (speedup 1.0000x reference)
#include <cuda_runtime.h>
#include <cuda_bf16.h>
#include <cstdint>
#include <math.h>

#define Hh 128
#define Ww 128
#define HW (Hh*Ww)
#define Cc 64
#define Oo 64
#define CK 576
#define PIX 32
#define NBLK (8*HW/PIX)   // 4096

// A planes (bf16): [32 px][580 elems] per plane (1160 B rows), hi then lo
#define AROWB   1160u
#define APLANE  (PIX*1160)               // 37120 B per plane
#define SM_OM   (2*APLANE)               // offmask buffer: [27][32] float
#define SMEM_F  (SM_OM + 27*32*4)        // 77696 B

extern __shared__ __align__(16) char _smem_raw[];

// DCN W fragments: [tile(8)][kk(36)][plane(2)][lane(32)] x uint2
__device__ __align__(16) uint2 g_wfrag[8*36*2*32];
// OffMask W fragments: [tile(4)][kk(36)][plane(2)][lane(32)] x uint2 (27 rows + pad)
__device__ __align__(16) uint2 g_wfrag_om[4*36*2*32];

// ---------------------------------------------------------------------------
// prep: pack weights into mma.sync B-fragment order, bf16 hi/lo planes.
// K ordered as k = tap*64 + c.
// ---------------------------------------------------------------------------
__device__ __forceinline__ float wdcn_at(const float* w_dcn, int o, int k) {
    int c = k & 63, tap = k >> 6;
    return w_dcn[o*CK + c*9 + tap];
}
__device__ __forceinline__ float wom_at(const float* w_off, const float* w_mask, int o, int k) {
    int c = k & 63, tap = k >> 6;
    if (o < 18) return w_off[o*CK + c*9 + tap];
    if (o < 27) return w_mask[(o-18)*CK + c*9 + tap];
    return 0.f;
}
__device__ __forceinline__ uint2 pack4(float w0, float w1, float w2, float w3, int plane) {
    __nv_bfloat16 v0, v1, v2, v3;
    if (plane == 0) {
        v0 = __float2bfloat16(w0); v1 = __float2bfloat16(w1);
        v2 = __float2bfloat16(w2); v3 = __float2bfloat16(w3);
    } else {
        v0 = __float2bfloat16(w0 - __bfloat162float(__float2bfloat16(w0)));
        v1 = __float2bfloat16(w1 - __bfloat162float(__float2bfloat16(w1)));
        v2 = __float2bfloat16(w2 - __bfloat162float(__float2bfloat16(w2)));
        v3 = __float2bfloat16(w3 - __bfloat162float(__float2bfloat16(w3)));
    }
    __nv_bfloat162 p0; p0.x = v0; p0.y = v1;
    __nv_bfloat162 p1; p1.x = v2; p1.y = v3;
    uint2 r;
    r.x = *(uint32_t*)&p0;
    r.y = *(uint32_t*)&p1;
    return r;
}

#define NFRAG_DCN (8*36*2*32)
#define NFRAG_OM  (4*36*2*32)

__global__ void prep_w(const float* __restrict__ w_dcn,
                       const float* __restrict__ w_off,
                       const float* __restrict__ w_mask) {
    int i = blockIdx.x*256 + threadIdx.x;
    if (i < NFRAG_DCN) {
        int lane  = i & 31;
        int plane = (i >> 5) & 1;
        int kt    = i >> 6;
        int kk    = kt % 36;
        int tile  = kt / 36;
        int g  = lane >> 2;
        int t4 = lane & 3;
        int o  = tile*8 + g;
        int k0 = kk*16 + t4*2;
        g_wfrag[i] = pack4(wdcn_at(w_dcn, o, k0),   wdcn_at(w_dcn, o, k0+1),
                           wdcn_at(w_dcn, o, k0+8), wdcn_at(w_dcn, o, k0+9), plane);
    } else if (i < NFRAG_DCN + NFRAG_OM) {
        int j = i - NFRAG_DCN;
        int lane  = j & 31;
        int plane = (j >> 5) & 1;
        int kt    = j >> 6;
        int kk    = kt % 36;
        int tile  = kt / 36;
        int g  = lane >> 2;
        int t4 = lane & 3;
        int o  = tile*8 + g;
        int k0 = kk*16 + t4*2;
        g_wfrag_om[j] = pack4(wom_at(w_off, w_mask, o, k0),   wom_at(w_off, w_mask, o, k0+1),
                              wom_at(w_off, w_mask, o, k0+8), wom_at(w_off, w_mask, o, k0+9), plane);
    }
}

#define MMA(dd, a0_,a1_,a2_,a3_, b_) \
    asm volatile("mma.sync.aligned.m16n8k16.row.col.f32.bf16.bf16.f32 " \
        "{%0,%1,%2,%3}, {%4,%5,%6,%7}, {%8,%9}, {%0,%1,%2,%3};" \
        : "+f"(dd[0]), "+f"(dd[1]), "+f"(dd[2]), "+f"(dd[3]) \
        : "r"(a0_), "r"(a1_), "r"(a2_), "r"(a3_), "r"(b_.x), "r"(b_.y))

// ---------------------------------------------------------------------------
// Fused kernel: im2col -> offmask GEMM (smem) -> deform sampling -> dcn GEMM
// Block = 32 pixels of one row. 256 threads.
// ---------------------------------------------------------------------------
__global__ __launch_bounds__(256) void fused_kernel(
    const float* __restrict__ x,
    const float* __restrict__ b_off, const float* __restrict__ b_mask,
    const float* __restrict__ b_dcn,
    float* __restrict__ out)
{
    char*  smA_h = _smem_raw;
    char*  smA_l = _smem_raw + APLANE;
    float* s_om  = (float*)(_smem_raw + SM_OM);   // [27][32]

    int blk = blockIdx.x;
    int b   = blk >> 9;
    int rem = blk & 511;
    int y   = rem >> 2;
    int x0  = (rem & 3) << 5;
    int tid = threadIdx.x;
    int wid  = tid >> 5;
    int lane = tid & 31;

    const float* xb = x + b*Cc*HW;

    // ---------------- Phase 1: im2col into bf16 hi/lo planes ----------------
    for (int task = tid; task < PIX*9; task += 256) {
        int p   = task & 31;
        int tap = task >> 5;
        int ki = tap / 3;
        int kj = tap - ki*3;
        int yy = y - 1 + ki;
        int xx = x0 + p - 1 + kj;
        uint32_t rowoff = (uint32_t)p*AROWB + (uint32_t)tap*128u;
        if (yy >= 0 && yy < Hh && xx >= 0 && xx < Ww) {
            const float* base = xb + yy*Ww + xx;
            #pragma unroll 8
            for (int c = 0; c < Cc; c += 2) {
                float v0 = base[c*HW];
                float v1 = base[(c+1)*HW];
                __nv_bfloat16 h0 = __float2bfloat16(v0);
                __nv_bfloat16 h1 = __float2bfloat16(v1);
                __nv_bfloat16 l0 = __float2bfloat16(v0 - __bfloat162float(h0));
                __nv_bfloat16 l1 = __float2bfloat16(v1 - __bfloat162float(h1));
                __nv_bfloat162 hh; hh.x = h0; hh.y = h1;
                __nv_bfloat162 ll; ll.x = l0; ll.y = l1;
                *(uint32_t*)(smA_h + rowoff + c*2) = *(uint32_t*)&hh;
                *(uint32_t*)(smA_l + rowoff + c*2) = *(uint32_t*)&ll;
            }
        } else {
            #pragma unroll 8
            for (int c = 0; c < Cc; c += 2) {
                *(uint32_t*)(smA_h + rowoff + c*2) = 0u;
                *(uint32_t*)(smA_l + rowoff + c*2) = 0u;
            }
        }
    }
    __syncthreads();

    // ---------------- Phase 2: offmask GEMM (27 outs, 8 warps m16 x n8) -----
    {
        int mrow = (wid & 1) * 16;
        int tile = wid >> 1;            // n8 tile 0..3
        int g  = lane >> 2;
        int t4 = lane & 3;

        float d[4] = {0.f,0.f,0.f,0.f};
        const uint2* fr = g_wfrag_om + (tile*36)*2*32 + lane;

        uint32_t arow0 = (uint32_t)(mrow + g)*AROWB + (uint32_t)t4*4u;
        uint32_t arow1 = arow0 + 8u*AROWB;

        #pragma unroll 4
        for (int kk = 0; kk < 36; kk++) {
            uint32_t koff = (uint32_t)kk*32u;
            uint32_t ah0 = *(const uint32_t*)(smA_h + arow0 + koff);
            uint32_t ah1 = *(const uint32_t*)(smA_h + arow1 + koff);
            uint32_t ah2 = *(const uint32_t*)(smA_h + arow0 + koff + 16u);
            uint32_t ah3 = *(const uint32_t*)(smA_h + arow1 + koff + 16u);
            uint32_t al0 = *(const uint32_t*)(smA_l + arow0 + koff);
            uint32_t al1 = *(const uint32_t*)(smA_l + arow1 + koff);
            uint32_t al2 = *(const uint32_t*)(smA_l + arow0 + koff + 16u);
            uint32_t al3 = *(const uint32_t*)(smA_l + arow1 + koff + 16u);

            uint2 bh = fr[(kk*2    )*32];
            uint2 bl = fr[(kk*2 + 1)*32];

            MMA(d, ah0,ah1,ah2,ah3, bh);
            MMA(d, ah0,ah1,ah2,ah3, bl);
            MMA(d, al0,al1,al2,al3, bh);
        }

        int pxl = mrow + g;
        #pragma unroll
        for (int e = 0; e < 2; e++) {
            int o = tile*8 + t4*2 + e;
            if (o < 27) {
                float bias = (o < 18) ? b_off[o] : b_mask[o-18];
                float r0 = d[e]   + bias;
                float r1 = d[e+2] + bias;
                if (o >= 18) {
                    r0 = 1.f/(1.f+expf(-r0));
                    r1 = 1.f/(1.f+expf(-r1));
                }
                s_om[o*32 + pxl    ] = r0;
                s_om[o*32 + pxl + 8] = r1;
            }
        }
    }
    __syncthreads();

    // ---------------- Phase 3: deformable sampling (overwrites A planes) ----
    for (int task = tid; task < PIX*9; task += 256) {
        int p = task & 31;
        int k = task >> 5;
        int xx = x0 + p;

        float dy = s_om[(2*k    )*32 + p];
        float dx = s_om[(2*k + 1)*32 + p];
        float m  = s_om[(18 + k )*32 + p];

        int ki = k / 3;
        int kj = k - ki*3;
        float py = (float)(y  - 1 + ki) + dy;
        float px = (float)(xx - 1 + kj) + dx;

        float fy = floorf(py), fx = floorf(px);
        float wy1 = py - fy, wx1 = px - fx;
        float wy0 = 1.f - wy1, wx0 = 1.f - wx1;

        float vy0 = (fy      >= 0.f && fy      <= 127.f) ? 1.f : 0.f;
        float vy1 = (fy+1.f  >= 0.f && fy+1.f  <= 127.f) ? 1.f : 0.f;
        float vx0 = (fx      >= 0.f && fx      <= 127.f) ? 1.f : 0.f;
        float vx1 = (fx+1.f  >= 0.f && fx+1.f  <= 127.f) ? 1.f : 0.f;

        int y0  = (int)fminf(fmaxf(fy,      0.f), 127.f);
        int y1  = (int)fminf(fmaxf(fy+1.f,  0.f), 127.f);
        int xq0 = (int)fminf(fmaxf(fx,      0.f), 127.f);
        int xq1 = (int)fminf(fmaxf(fx+1.f,  0.f), 127.f);

        int o00 = y0*Ww + xq0, o01 = y0*Ww + xq1;
        int o10 = y1*Ww + xq0, o11 = y1*Ww + xq1;
        float w00 = wy0*wx0*vy0*vx0*m;
        float w01 = wy0*wx1*vy0*vx1*m;
        float w10 = wy1*wx0*vy1*vx0*m;
        float w11 = wy1*wx1*vy1*vx1*m;

        uint32_t rowoff = (uint32_t)p*AROWB + (uint32_t)k*128u;
        const float* xc = xb;
        #pragma unroll 8
        for (int c = 0; c < Cc; c += 2) {
            const float* c0 = xc;
            const float* c1 = xc + HW;
            float v0 = w00*c0[o00] + w01*c0[o01] + w10*c0[o10] + w11*c0[o11];
            float v1 = w00*c1[o00] + w01*c1[o01] + w10*c1[o10] + w11*c1[o11];
            __nv_bfloat16 h0 = __float2bfloat16(v0);
            __nv_bfloat16 h1 = __float2bfloat16(v1);
            __nv_bfloat16 l0 = __float2bfloat16(v0 - __bfloat162float(h0));
            __nv_bfloat16 l1 = __float2bfloat16(v1 - __bfloat162float(h1));
            __nv_bfloat162 hh; hh.x = h0; hh.y = h1;
            __nv_bfloat162 ll; ll.x = l0; ll.y = l1;
            *(uint32_t*)(smA_h + rowoff + c*2) = *(uint32_t*)&hh;
            *(uint32_t*)(smA_l + rowoff + c*2) = *(uint32_t*)&ll;
            xc += 2*HW;
        }
    }
    __syncthreads();

    // ---------------- Phase 4: main DCN GEMM (8 warps m16 x n16) ------------
    {
        int mrow = (wid & 1) * 16;
        int ng   = wid >> 1;
        int g  = lane >> 2;
        int t4 = lane & 3;

        float d0[4] = {0.f,0.f,0.f,0.f};
        float d1[4] = {0.f,0.f,0.f,0.f};

        const uint2* fr0 = g_wfrag + ((ng*2    )*36)*2*32 + lane;
        const uint2* fr1 = g_wfrag + ((ng*2 + 1)*36)*2*32 + lane;

        uint32_t arow0 = (uint32_t)(mrow + g)*AROWB + (uint32_t)t4*4u;
        uint32_t arow1 = arow0 + 8u*AROWB;

        #pragma unroll 4
        for (int kk = 0; kk < 36; kk++) {
            uint32_t koff = (uint32_t)kk*32u;
            uint32_t ah0 = *(const uint32_t*)(smA_h + arow0 + koff);
            uint32_t ah1 = *(const uint32_t*)(smA_h + arow1 + koff);
            uint32_t ah2 = *(const uint32_t*)(smA_h + arow0 + koff + 16u);
            uint32_t ah3 = *(const uint32_t*)(smA_h + arow1 + koff + 16u);
            uint32_t al0 = *(const uint32_t*)(smA_l + arow0 + koff);
            uint32_t al1 = *(const uint32_t*)(smA_l + arow1 + koff);
            uint32_t al2 = *(const uint32_t*)(smA_l + arow0 + koff + 16u);
            uint32_t al3 = *(const uint32_t*)(smA_l + arow1 + koff + 16u);

            uint2 bh0 = fr0[(kk*2    )*32];
            uint2 bl0 = fr0[(kk*2 + 1)*32];
            uint2 bh1 = fr1[(kk*2    )*32];
            uint2 bl1 = fr1[(kk*2 + 1)*32];

            MMA(d0, ah0,ah1,ah2,ah3, bh0);
            MMA(d0, ah0,ah1,ah2,ah3, bl0);
            MMA(d0, al0,al1,al2,al3, bh0);
            MMA(d1, ah0,ah1,ah2,ah3, bh1);
            MMA(d1, ah0,ah1,ah2,ah3, bl1);
            MMA(d1, al0,al1,al2,al3, bh1);
        }

        int px0 = x0 + mrow + g;
        int obase = b*Oo*HW + y*Ww;
        #pragma unroll
        for (int j = 0; j < 2; j++) {
            float* dd = j ? d1 : d0;
            int on = ng*16 + j*8 + t4*2;
            float bia0 = b_dcn[on];
            float bia1 = b_dcn[on+1];
            out[obase + on*HW     + px0    ] = dd[0] + bia0;
            out[obase + (on+1)*HW + px0    ] = dd[1] + bia1;
            out[obase + on*HW     + px0 + 8] = dd[2] + bia0;
            out[obase + (on+1)*HW + px0 + 8] = dd[3] + bia1;
        }
    }
}

extern "C" void kernel_launch(void* const* d_in, const int* in_sizes, int n_in,
                              void* d_out, int out_size)
{
    const float* x      = (const float*)d_in[0];
    const float* w_off  = (const float*)d_in[1];
    const float* b_off  = (const float*)d_in[2];
    const float* w_mask = (const float*)d_in[3];
    const float* b_mask = (const float*)d_in[4];
    const float* w_dcn  = (const float*)d_in[5];
    const float* b_dcn  = (const float*)d_in[6];
    float* out = (float*)d_out;

    cudaFuncSetAttribute(fused_kernel, cudaFuncAttributeMaxDynamicSharedMemorySize, SMEM_F);

    prep_w<<<108, 256>>>(w_dcn, w_off, w_mask);
    fused_kernel<<<NBLK, 256, SMEM_F>>>(x, b_off, b_mask, b_dcn, out);
}